// round 1
// baseline (speedup 1.0000x reference)
#include <cuda_runtime.h>
#include <math.h>

// Problem constants
#define BB 32
#define SS 512
#define DD 256
#define HH 512
#define NHH 8
#define HDD 64
#define PFF 2048
#define LL 2
#define NTOK (BB*SS)      // 16384
#define NMAXX 15

// Scratch (device globals; no allocation allowed)
__device__ float g_x[NTOK*DD];
__device__ float g_agg[NTOK*DD];
__device__ float g_soc[NTOK*DD];
__device__ float g_h[NTOK*HH];
__device__ float g_q[NTOK*HH];
__device__ float g_k[NTOK*HH];
__device__ float g_v[NTOK*HH];
__device__ float g_ao[NTOK*HH];
__device__ float g_t[NTOK*HH];
__device__ float g_ff[NTOK*PFF];

// ---------------------------------------------------------------------------
// 1) embedding + sinusoidal PE + time-interval encoding
// ---------------------------------------------------------------------------
__global__ void embed_kernel(const int* __restrict__ src, const float* __restrict__ tint,
                             const float* __restrict__ emb, const float* __restrict__ timeW,
                             const float* __restrict__ timeb, float* __restrict__ x) {
    int idx = blockIdx.x * blockDim.x + threadIdx.x;
    if (idx >= NTOK * DD) return;
    int n = idx / DD, d = idx - n * DD;
    int s = n & (SS - 1);
    int tok = src[n];
    float div = expf((float)(d & ~1) * (-9.210340371976184f / (float)DD)); // ln(10000)
    float arg = (float)s * div;
    float pe = (d & 1) ? cosf(arg) : sinf(arg);
    x[idx] = emb[tok * DD + d] + pe + tint[n] * timeW[d] + timeb[d];
}

// ---------------------------------------------------------------------------
// 2) neighbor aggregation: masked mean over <=15 neighbors
// ---------------------------------------------------------------------------
__global__ void agg_kernel(const int* __restrict__ nb, const int* __restrict__ cnt,
                           const float* __restrict__ x, float* __restrict__ agg) {
    int n = blockIdx.x;
    int d = threadIdx.x;            // 256 threads == DD
    int c = cnt[n];
    float s = 0.f;
    for (int j = 0; j < c; j++) {
        int m = nb[n * NMAXX + j];
        s += x[m * DD + d];
    }
    int cm = c > 0 ? c : 1;
    agg[n * DD + d] = s / (float)cm;
}

// ---------------------------------------------------------------------------
// SGEMM: C[M,Nn] = A[M,K] * B[K,Nn] + bias (optional ReLU). All dims multiples
// of tile sizes here (M=16384; Nn in {256,512,2048}; K in {256,512,2048}).
// 128x128 tile, BK=8, 256 threads, 8x8 per thread, 4+4 split (conflict-free).
// ---------------------------------------------------------------------------
template<bool RELU>
__global__ __launch_bounds__(256) void sgemm_kernel(
    const float* __restrict__ A, const float* __restrict__ B,
    const float* __restrict__ bias, float* __restrict__ C,
    int M, int Nn, int K) {
    __shared__ float As[8][128];
    __shared__ float Bs[8][128];
    int tid = threadIdx.x;
    int bm = blockIdx.y * 128, bn = blockIdx.x * 128;
    int tx = tid & 15, ty = tid >> 4;
    int arow = tid >> 1, acol = (tid & 1) * 4;
    int brow = tid >> 5, bcol = (tid & 31) * 4;
    const float* Aptr = A + (size_t)(bm + arow) * K + acol;
    const float* Bptr = B + (size_t)brow * Nn + bn + bcol;

    float acc[8][8];
    #pragma unroll
    for (int i = 0; i < 8; i++)
        #pragma unroll
        for (int j = 0; j < 8; j++) acc[i][j] = 0.f;

    for (int k0 = 0; k0 < K; k0 += 8) {
        float4 av = *(const float4*)(Aptr + k0);
        float4 bv = *(const float4*)(Bptr + (size_t)k0 * Nn);
        As[acol + 0][arow] = av.x;
        As[acol + 1][arow] = av.y;
        As[acol + 2][arow] = av.z;
        As[acol + 3][arow] = av.w;
        *(float4*)&Bs[brow][bcol] = bv;
        __syncthreads();
        #pragma unroll
        for (int kk = 0; kk < 8; kk++) {
            float ra[8], rb[8];
            #pragma unroll
            for (int i = 0; i < 4; i++) {
                ra[i]     = As[kk][ty * 4 + i];
                ra[4 + i] = As[kk][64 + ty * 4 + i];
                rb[i]     = Bs[kk][tx * 4 + i];
                rb[4 + i] = Bs[kk][64 + tx * 4 + i];
            }
            #pragma unroll
            for (int i = 0; i < 8; i++)
                #pragma unroll
                for (int j = 0; j < 8; j++)
                    acc[i][j] += ra[i] * rb[j];
        }
        __syncthreads();
    }

    // epilogue: two float4 stores per row (cols tx*4.. and 64+tx*4..)
    #pragma unroll
    for (int i = 0; i < 8; i++) {
        int row = bm + ((i < 4) ? (ty * 4 + i) : (64 + ty * 4 + i - 4));
        float* crow = C + (size_t)row * Nn + bn;
        int c0 = tx * 4, c1 = 64 + tx * 4;
        float4 o0, o1;
        float vx;
        vx = acc[i][0] + bias[bn + c0 + 0]; o0.x = RELU ? fmaxf(vx, 0.f) : vx;
        vx = acc[i][1] + bias[bn + c0 + 1]; o0.y = RELU ? fmaxf(vx, 0.f) : vx;
        vx = acc[i][2] + bias[bn + c0 + 2]; o0.z = RELU ? fmaxf(vx, 0.f) : vx;
        vx = acc[i][3] + bias[bn + c0 + 3]; o0.w = RELU ? fmaxf(vx, 0.f) : vx;
        vx = acc[i][4] + bias[bn + c1 + 0]; o1.x = RELU ? fmaxf(vx, 0.f) : vx;
        vx = acc[i][5] + bias[bn + c1 + 1]; o1.y = RELU ? fmaxf(vx, 0.f) : vx;
        vx = acc[i][6] + bias[bn + c1 + 2]; o1.z = RELU ? fmaxf(vx, 0.f) : vx;
        vx = acc[i][7] + bias[bn + c1 + 3]; o1.w = RELU ? fmaxf(vx, 0.f) : vx;
        *(float4*)&crow[c0] = o0;
        *(float4*)&crow[c1] = o1;
    }
}

// ---------------------------------------------------------------------------
// 3) social block epilogue: y = x + (agg@W + b); soc = relu(LN(y))
//    soc = cnt>0 ? soc : x ;  soc = (src!=PAD) ? soc : 0 ; x += 0.2*soc
// ---------------------------------------------------------------------------
__global__ void soc_finish_kernel(const int* __restrict__ src, const int* __restrict__ cnt,
                                  const float* __restrict__ g, const float* __restrict__ beta,
                                  float* __restrict__ x, const float* __restrict__ socl) {
    __shared__ float red[256];
    int n = blockIdx.x, t = threadIdx.x;
    float flatv = x[n * DD + t];
    float y = flatv + socl[n * DD + t];
    red[t] = y; __syncthreads();
    for (int s = 128; s; s >>= 1) { if (t < s) red[t] += red[t + s]; __syncthreads(); }
    float mu = red[0] * (1.f / DD);
    __syncthreads();
    float e = y - mu;
    red[t] = e * e; __syncthreads();
    for (int s = 128; s; s >>= 1) { if (t < s) red[t] += red[t + s]; __syncthreads(); }
    float rstd = rsqrtf(red[0] * (1.f / DD) + 1e-5f);
    float s1 = fmaxf(e * rstd * g[t] + beta[t], 0.f);
    float soc = (cnt[n] > 0) ? s1 : flatv;
    if (src[n] == 0) soc = 0.f;
    x[n * DD + t] = flatv + 0.2f * soc;
}

// ---------------------------------------------------------------------------
// residual-add + LayerNorm for H=512 rows (two-pass, 256 threads, 2 elems/thr)
// ---------------------------------------------------------------------------
__global__ void add_ln512_kernel(const float* __restrict__ resid, const float* __restrict__ delta,
                                 const float* __restrict__ g, const float* __restrict__ bta,
                                 float* __restrict__ out) {
    __shared__ float red[256];
    int n = blockIdx.x, t = threadIdx.x;
    float y0 = resid[n * 512 + t]       + delta[n * 512 + t];
    float y1 = resid[n * 512 + 256 + t] + delta[n * 512 + 256 + t];
    red[t] = y0 + y1; __syncthreads();
    for (int s = 128; s; s >>= 1) { if (t < s) red[t] += red[t + s]; __syncthreads(); }
    float mu = red[0] * (1.f / 512.f);
    __syncthreads();
    float e0 = y0 - mu, e1 = y1 - mu;
    red[t] = e0 * e0 + e1 * e1; __syncthreads();
    for (int s = 128; s; s >>= 1) { if (t < s) red[t] += red[t + s]; __syncthreads(); }
    float rstd = rsqrtf(red[0] * (1.f / 512.f) + 1e-5f);
    out[n * 512 + t]       = e0 * rstd * g[t] + bta[t];
    out[n * 512 + 256 + t] = e1 * rstd * g[256 + t] + bta[256 + t];
}

// ---------------------------------------------------------------------------
// 4) masked flash attention: block = (qtile of 64, head, batch), 128 threads.
//    Online softmax over 16 key-tiles of 32. All fp32.
// ---------------------------------------------------------------------------
__global__ __launch_bounds__(128) void attn_kernel(
    const float* __restrict__ q, const float* __restrict__ k,
    const float* __restrict__ v, const int* __restrict__ src,
    float* __restrict__ o) {
    __shared__ float Qs[64][68];
    __shared__ float Ks[32][68];
    __shared__ float Vs[32][68];
    __shared__ float Ps[64][33];
    __shared__ float m_s[64], l_s[64], sc_s[64];
    __shared__ int msk[32];
    int b = blockIdx.z, hh = blockIdx.y, qt = blockIdx.x;
    int tid = threadIdx.x;
    int qbase = b * SS + qt * 64;

    for (int i = tid; i < 64 * 16; i += 128) {         // Q tile: 1024 float4
        int r = i >> 4, c = (i & 15) << 2;
        *(float4*)&Qs[r][c] = *(const float4*)&q[(size_t)(qbase + r) * HH + hh * 64 + c];
    }
    if (tid < 64) { m_s[tid] = -1e30f; l_s[tid] = 0.f; }
    int qrow = tid >> 1, half = tid & 1, d0 = half * 32;
    float acc[32];
    #pragma unroll
    for (int j = 0; j < 32; j++) acc[j] = 0.f;
    __syncthreads();

    float4 qreg[16];
    #pragma unroll
    for (int i = 0; i < 16; i++) qreg[i] = *(const float4*)&Qs[qrow][i * 4];

    for (int kt = 0; kt < 16; kt++) {
        int kbase = b * SS + kt * 32;
        for (int i = tid; i < 32 * 16; i += 128) {
            int r = i >> 4, c = (i & 15) << 2;
            size_t off = (size_t)(kbase + r) * HH + hh * 64 + c;
            *(float4*)&Ks[r][c] = *(const float4*)&k[off];
            *(float4*)&Vs[r][c] = *(const float4*)&v[off];
        }
        if (tid < 32) msk[tid] = (src[kbase + tid] != 0);
        __syncthreads();

        // scores: 16 per thread
        for (int kk = 0; kk < 16; kk++) {
            int key = half * 16 + kk;
            const float4* kp = (const float4*)&Ks[key][0];
            float s = 0.f;
            #pragma unroll
            for (int i = 0; i < 16; i++) {
                float4 kv = kp[i];
                s += qreg[i].x * kv.x + qreg[i].y * kv.y + qreg[i].z * kv.z + qreg[i].w * kv.w;
            }
            Ps[qrow][key] = msk[key] ? s * 0.125f : -1e10f;
        }
        __syncthreads();

        // online softmax per query row
        if (tid < 64) {
            float mt = -1e30f;
            for (int kk = 0; kk < 32; kk++) mt = fmaxf(mt, Ps[tid][kk]);
            float mold = m_s[tid], mnew = fmaxf(mold, mt);
            float sc = expf(mold - mnew);
            float ls = 0.f;
            for (int kk = 0; kk < 32; kk++) {
                float p = expf(Ps[tid][kk] - mnew);
                Ps[tid][kk] = p;
                ls += p;
            }
            m_s[tid] = mnew;
            l_s[tid] = l_s[tid] * sc + ls;
            sc_s[tid] = sc;
        }
        __syncthreads();

        float sc = sc_s[qrow];
        #pragma unroll
        for (int j = 0; j < 32; j++) acc[j] *= sc;
        for (int kk = 0; kk < 32; kk++) {
            float p = Ps[qrow][kk];
            const float4* vp = (const float4*)&Vs[kk][d0];
            #pragma unroll
            for (int j4 = 0; j4 < 8; j4++) {
                float4 vv = vp[j4];
                acc[j4 * 4 + 0] += p * vv.x;
                acc[j4 * 4 + 1] += p * vv.y;
                acc[j4 * 4 + 2] += p * vv.z;
                acc[j4 * 4 + 3] += p * vv.w;
            }
        }
        __syncthreads();
    }

    float inv = 1.f / l_s[qrow];
    float* op = &o[(size_t)(qbase + qrow) * HH + hh * 64 + d0];
    #pragma unroll
    for (int j4 = 0; j4 < 8; j4++) {
        float4 w;
        w.x = acc[j4 * 4 + 0] * inv;
        w.y = acc[j4 * 4 + 1] * inv;
        w.z = acc[j4 * 4 + 2] * inv;
        w.w = acc[j4 * 4 + 3] * inv;
        *(float4*)&op[j4 * 4] = w;
    }
}

// ---------------------------------------------------------------------------
// output: concat(h [N*H], x [N*D])
// ---------------------------------------------------------------------------
__global__ void copy_out_kernel(const float* __restrict__ h, const float* __restrict__ x,
                                float* __restrict__ out) {
    int i = blockIdx.x * blockDim.x + threadIdx.x;
    if (i < NTOK * HH) out[i] = h[i];
    else if (i < NTOK * HH + NTOK * DD) out[i] = x[i - NTOK * HH];
}

// ---------------------------------------------------------------------------
extern "C" void kernel_launch(void* const* d_in, const int* in_sizes, int n_in,
                              void* d_out, int out_size) {
    const int*   src   = (const int*)  d_in[0];
    // d_in[1] = src_lengths (unused by reference)
    const int*   nb    = (const int*)  d_in[2];
    const int*   cnt   = (const int*)  d_in[3];
    const float* tint  = (const float*)d_in[4];
    const float* emb   = (const float*)d_in[5];
    const float* timeW = (const float*)d_in[6];
    const float* timeb = (const float*)d_in[7];
    const float* socW  = (const float*)d_in[8];
    const float* socb  = (const float*)d_in[9];
    const float* socg  = (const float*)d_in[10];
    const float* socbe = (const float*)d_in[11];
    const float* projW = (const float*)d_in[12];
    const float* projb = (const float*)d_in[13];
    const float* Wq    = (const float*)d_in[14];
    const float* bq    = (const float*)d_in[15];
    const float* Wk    = (const float*)d_in[16];
    const float* bk    = (const float*)d_in[17];
    const float* Wv    = (const float*)d_in[18];
    const float* bv    = (const float*)d_in[19];
    const float* Wo    = (const float*)d_in[20];
    const float* bo    = (const float*)d_in[21];
    const float* ln1g  = (const float*)d_in[22];
    const float* ln1b  = (const float*)d_in[23];
    const float* ffW1  = (const float*)d_in[24];
    const float* ffb1  = (const float*)d_in[25];
    const float* ffW2  = (const float*)d_in[26];
    const float* ffb2  = (const float*)d_in[27];
    const float* ln2g  = (const float*)d_in[28];
    const float* ln2b  = (const float*)d_in[29];

    float *px, *pagg, *psoc, *ph, *pq, *pk, *pv, *pao, *pt, *pff;
    cudaGetSymbolAddress((void**)&px,   g_x);
    cudaGetSymbolAddress((void**)&pagg, g_agg);
    cudaGetSymbolAddress((void**)&psoc, g_soc);
    cudaGetSymbolAddress((void**)&ph,   g_h);
    cudaGetSymbolAddress((void**)&pq,   g_q);
    cudaGetSymbolAddress((void**)&pk,   g_k);
    cudaGetSymbolAddress((void**)&pv,   g_v);
    cudaGetSymbolAddress((void**)&pao,  g_ao);
    cudaGetSymbolAddress((void**)&pt,   g_t);
    cudaGetSymbolAddress((void**)&pff,  g_ff);

    // 1) embedding + PE + time
    embed_kernel<<<(NTOK * DD + 255) / 256, 256>>>(src, tint, emb, timeW, timeb, px);
    // 2) neighbor mean
    agg_kernel<<<NTOK, 256>>>(nb, cnt, px, pagg);
    // 3) soc = agg @ soc_W + soc_b  -> LN/relu/select -> x += 0.2*soc
    sgemm_kernel<false><<<dim3(DD / 128, NTOK / 128), 256>>>(pagg, socW, socb, psoc, NTOK, DD, DD);
    soc_finish_kernel<<<NTOK, 256>>>(src, cnt, socg, socbe, px, psoc);
    // 4) h = x @ proj_W + proj_b
    sgemm_kernel<false><<<dim3(HH / 128, NTOK / 128), 256>>>(px, projW, projb, ph, NTOK, HH, DD);

    for (int l = 0; l < LL; l++) {
        const float* wq = Wq + (size_t)l * HH * HH;
        const float* wk = Wk + (size_t)l * HH * HH;
        const float* wv = Wv + (size_t)l * HH * HH;
        const float* wo = Wo + (size_t)l * HH * HH;
        sgemm_kernel<false><<<dim3(HH / 128, NTOK / 128), 256>>>(ph, wq, bq + l * HH, pq, NTOK, HH, HH);
        sgemm_kernel<false><<<dim3(HH / 128, NTOK / 128), 256>>>(ph, wk, bk + l * HH, pk, NTOK, HH, HH);
        sgemm_kernel<false><<<dim3(HH / 128, NTOK / 128), 256>>>(ph, wv, bv + l * HH, pv, NTOK, HH, HH);
        attn_kernel<<<dim3(SS / 64, NHH, BB), 128>>>(pq, pk, pv, src, pao);
        sgemm_kernel<false><<<dim3(HH / 128, NTOK / 128), 256>>>(pao, wo, bo + l * HH, pt, NTOK, HH, HH);
        add_ln512_kernel<<<NTOK, 256>>>(ph, pt, ln1g + l * HH, ln1b + l * HH, ph);
        sgemm_kernel<true><<<dim3(PFF / 128, NTOK / 128), 256>>>(ph, ffW1 + (size_t)l * HH * PFF,
                                                                 ffb1 + l * PFF, pff, NTOK, PFF, HH);
        sgemm_kernel<false><<<dim3(HH / 128, NTOK / 128), 256>>>(pff, ffW2 + (size_t)l * PFF * HH,
                                                                 ffb2 + l * HH, pt, NTOK, HH, PFF);
        add_ln512_kernel<<<NTOK, 256>>>(ph, pt, ln2g + l * HH, ln2b + l * HH, ph);
    }

    int total = NTOK * HH + NTOK * DD;
    copy_out_kernel<<<(total + 255) / 256, 256>>>(ph, px, (float*)d_out);
}

// round 2
// speedup vs baseline: 1.6928x; 1.6928x over previous
#include <cuda_runtime.h>
#include <math.h>
#include <stdint.h>

// Problem constants
#define BB 32
#define SS 512
#define DD 256
#define HH 512
#define NHH 8
#define HDD 64
#define PFF 2048
#define LL 2
#define NTOK (BB*SS)      // 16384
#define NMAXX 15

// Scratch (device globals; no allocation allowed)
__device__ float g_x[NTOK*DD];
__device__ float g_agg[NTOK*DD];
__device__ float g_soc[NTOK*DD];
__device__ float g_h[NTOK*HH];
__device__ float g_q[NTOK*HH];
__device__ float g_k[NTOK*HH];
__device__ float g_v[NTOK*HH];
__device__ float g_ao[NTOK*HH];
__device__ float g_t[NTOK*HH];
__device__ float g_ff[NTOK*PFF];

// ---------------------------------------------------------------------------
// helpers
// ---------------------------------------------------------------------------
__device__ __forceinline__ float to_tf32(float x) {
    uint32_t u;
    asm("cvt.rna.tf32.f32 %0, %1;" : "=r"(u) : "f"(x));
    return __uint_as_float(u);
}

__device__ __forceinline__ void mma_tf32(float* c, const float* a, const float* b) {
    const uint32_t* A = reinterpret_cast<const uint32_t*>(a);
    const uint32_t* B = reinterpret_cast<const uint32_t*>(b);
    asm volatile(
        "mma.sync.aligned.m16n8k8.row.col.f32.tf32.tf32.f32 "
        "{%0,%1,%2,%3}, {%4,%5,%6,%7}, {%8,%9}, {%0,%1,%2,%3};"
        : "+f"(c[0]), "+f"(c[1]), "+f"(c[2]), "+f"(c[3])
        : "r"(A[0]), "r"(A[1]), "r"(A[2]), "r"(A[3]), "r"(B[0]), "r"(B[1]));
}

// ---------------------------------------------------------------------------
// 1) embedding + sinusoidal PE + time-interval encoding
// ---------------------------------------------------------------------------
__global__ void embed_kernel(const int* __restrict__ src, const float* __restrict__ tint,
                             const float* __restrict__ emb, const float* __restrict__ timeW,
                             const float* __restrict__ timeb, float* __restrict__ x) {
    int idx = blockIdx.x * blockDim.x + threadIdx.x;
    if (idx >= NTOK * DD) return;
    int n = idx / DD, d = idx - n * DD;
    int s = n & (SS - 1);
    int tok = src[n];
    float div = expf((float)(d & ~1) * (-9.210340371976184f / (float)DD)); // ln(10000)
    float arg = (float)s * div;
    float pe = (d & 1) ? cosf(arg) : sinf(arg);
    x[idx] = emb[tok * DD + d] + pe + tint[n] * timeW[d] + timeb[d];
}

// ---------------------------------------------------------------------------
// 2) neighbor aggregation: masked mean over <=15 neighbors
// ---------------------------------------------------------------------------
__global__ void agg_kernel(const int* __restrict__ nb, const int* __restrict__ cnt,
                           const float* __restrict__ x, float* __restrict__ agg) {
    int n = blockIdx.x;
    int d = threadIdx.x;            // 256 threads == DD
    int c = cnt[n];
    float s = 0.f;
    for (int j = 0; j < c; j++) {
        int m = nb[n * NMAXX + j];
        s += x[m * DD + d];
    }
    int cm = c > 0 ? c : 1;
    agg[n * DD + d] = s / (float)cm;
}

// ---------------------------------------------------------------------------
// TF32 tensor-core GEMM: C[M,Nn] = A[M,K] * B[K,Nn] + bias (optional ReLU)
// 128x128 CTA tile, BK=32, 256 threads = 8 warps (2x4), warp tile 64x32.
// mma.sync.m16n8k8.tf32, fp32 accumulate. Conflict-free fragment LDS.
// All shapes here: M=16384; Nn in {256,512,2048}; K in {256,512,2048}.
// ---------------------------------------------------------------------------
#define APAD 4   // A row stride = 36 words -> frag bank = (4g+t) conflict-free
#define BPAD 8   // B row stride = 136 words -> frag bank = (8t+g) conflict-free

template<bool RELU>
__global__ __launch_bounds__(256) void tgemm_kernel(
    const float* __restrict__ A, const float* __restrict__ B,
    const float* __restrict__ bias, float* __restrict__ C,
    int M, int Nn, int K) {
    __shared__ float As[128][32 + APAD];
    __shared__ float Bs[32][128 + BPAD];

    int tid = threadIdx.x;
    int lane = tid & 31, warp = tid >> 5;
    int wm = (warp >> 2) * 64;      // warp row offset within CTA tile
    int wn = (warp & 3) * 32;       // warp col offset
    int g = lane >> 2, t = lane & 3;
    int bm = blockIdx.y * 128, bn = blockIdx.x * 128;

    // global load indexing
    int arow = tid >> 1;            // 0..127, 2 threads per A row
    int acol0 = (tid & 1) * 16;     // each thread covers 16 cols (4 float4)
    int brow = tid >> 3;            // 0..31, 8 threads per B row
    int bcol0 = (tid & 7) * 4;      // float4 col base, stride 32 floats

    float acc[4][4][4];
    #pragma unroll
    for (int mi = 0; mi < 4; mi++)
        #pragma unroll
        for (int ni = 0; ni < 4; ni++)
            #pragma unroll
            for (int r = 0; r < 4; r++) acc[mi][ni][r] = 0.f;

    const float* Ag = A + (size_t)(bm + arow) * K + acol0;
    const float* Bg = B + (size_t)brow * Nn + bn + bcol0;

    for (int k0 = 0; k0 < K; k0 += 32) {
        // stage A tile (convert to tf32)
        #pragma unroll
        for (int i = 0; i < 4; i++) {
            float4 v = *(const float4*)(Ag + k0 + i * 4);
            As[arow][acol0 + i * 4 + 0] = to_tf32(v.x);
            As[arow][acol0 + i * 4 + 1] = to_tf32(v.y);
            As[arow][acol0 + i * 4 + 2] = to_tf32(v.z);
            As[arow][acol0 + i * 4 + 3] = to_tf32(v.w);
        }
        // stage B tile (convert to tf32)
        #pragma unroll
        for (int i = 0; i < 4; i++) {
            float4 v = *(const float4*)(Bg + (size_t)k0 * Nn + i * 32);
            Bs[brow][bcol0 + i * 32 + 0] = to_tf32(v.x);
            Bs[brow][bcol0 + i * 32 + 1] = to_tf32(v.y);
            Bs[brow][bcol0 + i * 32 + 2] = to_tf32(v.z);
            Bs[brow][bcol0 + i * 32 + 3] = to_tf32(v.w);
        }
        __syncthreads();

        #pragma unroll
        for (int kk = 0; kk < 4; kk++) {
            int k = kk * 8;
            float af[4][4];
            #pragma unroll
            for (int mi = 0; mi < 4; mi++) {
                int r0 = wm + mi * 16 + g;
                af[mi][0] = As[r0][k + t];
                af[mi][1] = As[r0 + 8][k + t];
                af[mi][2] = As[r0][k + t + 4];
                af[mi][3] = As[r0 + 8][k + t + 4];
            }
            float bf[4][2];
            #pragma unroll
            for (int ni = 0; ni < 4; ni++) {
                int c = wn + ni * 8 + g;
                bf[ni][0] = Bs[k + t][c];
                bf[ni][1] = Bs[k + t + 4][c];
            }
            #pragma unroll
            for (int mi = 0; mi < 4; mi++)
                #pragma unroll
                for (int ni = 0; ni < 4; ni++)
                    mma_tf32(acc[mi][ni], af[mi], bf[ni]);
        }
        __syncthreads();
    }

    // epilogue: bias (+relu), float2 stores
    #pragma unroll
    for (int mi = 0; mi < 4; mi++) {
        int r0 = bm + wm + mi * 16 + g;
        int r1 = r0 + 8;
        #pragma unroll
        for (int ni = 0; ni < 4; ni++) {
            int c = bn + wn + ni * 8 + 2 * t;
            float bx = bias[c], by = bias[c + 1];
            float v0 = acc[mi][ni][0] + bx;
            float v1 = acc[mi][ni][1] + by;
            float v2 = acc[mi][ni][2] + bx;
            float v3 = acc[mi][ni][3] + by;
            if (RELU) {
                v0 = fmaxf(v0, 0.f); v1 = fmaxf(v1, 0.f);
                v2 = fmaxf(v2, 0.f); v3 = fmaxf(v3, 0.f);
            }
            *(float2*)&C[(size_t)r0 * Nn + c] = make_float2(v0, v1);
            *(float2*)&C[(size_t)r1 * Nn + c] = make_float2(v2, v3);
        }
    }
}

// ---------------------------------------------------------------------------
// 3) social block epilogue: y = x + (agg@W + b); soc = relu(LN(y))
// ---------------------------------------------------------------------------
__global__ void soc_finish_kernel(const int* __restrict__ src, const int* __restrict__ cnt,
                                  const float* __restrict__ g, const float* __restrict__ beta,
                                  float* __restrict__ x, const float* __restrict__ socl) {
    __shared__ float red[256];
    int n = blockIdx.x, t = threadIdx.x;
    float flatv = x[n * DD + t];
    float y = flatv + socl[n * DD + t];
    red[t] = y; __syncthreads();
    for (int s = 128; s; s >>= 1) { if (t < s) red[t] += red[t + s]; __syncthreads(); }
    float mu = red[0] * (1.f / DD);
    __syncthreads();
    float e = y - mu;
    red[t] = e * e; __syncthreads();
    for (int s = 128; s; s >>= 1) { if (t < s) red[t] += red[t + s]; __syncthreads(); }
    float rstd = rsqrtf(red[0] * (1.f / DD) + 1e-5f);
    float s1 = fmaxf(e * rstd * g[t] + beta[t], 0.f);
    float soc = (cnt[n] > 0) ? s1 : flatv;
    if (src[n] == 0) soc = 0.f;
    x[n * DD + t] = flatv + 0.2f * soc;
}

// ---------------------------------------------------------------------------
// residual-add + LayerNorm for H=512 rows
// ---------------------------------------------------------------------------
__global__ void add_ln512_kernel(const float* __restrict__ resid, const float* __restrict__ delta,
                                 const float* __restrict__ g, const float* __restrict__ bta,
                                 float* __restrict__ out) {
    __shared__ float red[256];
    int n = blockIdx.x, t = threadIdx.x;
    float y0 = resid[n * 512 + t]       + delta[n * 512 + t];
    float y1 = resid[n * 512 + 256 + t] + delta[n * 512 + 256 + t];
    red[t] = y0 + y1; __syncthreads();
    for (int s = 128; s; s >>= 1) { if (t < s) red[t] += red[t + s]; __syncthreads(); }
    float mu = red[0] * (1.f / 512.f);
    __syncthreads();
    float e0 = y0 - mu, e1 = y1 - mu;
    red[t] = e0 * e0 + e1 * e1; __syncthreads();
    for (int s = 128; s; s >>= 1) { if (t < s) red[t] += red[t + s]; __syncthreads(); }
    float rstd = rsqrtf(red[0] * (1.f / 512.f) + 1e-5f);
    out[n * 512 + t]       = e0 * rstd * g[t] + bta[t];
    out[n * 512 + 256 + t] = e1 * rstd * g[256 + t] + bta[256 + t];
}

// ---------------------------------------------------------------------------
// 4) masked flash attention (fp32): block = (qtile 64, head, batch), 128 thr
// ---------------------------------------------------------------------------
__global__ __launch_bounds__(128) void attn_kernel(
    const float* __restrict__ q, const float* __restrict__ k,
    const float* __restrict__ v, const int* __restrict__ src,
    float* __restrict__ o) {
    __shared__ float Qs[64][68];
    __shared__ float Ks[32][68];
    __shared__ float Vs[32][68];
    __shared__ float Ps[64][33];
    __shared__ float m_s[64], l_s[64], sc_s[64];
    __shared__ int msk[32];
    int b = blockIdx.z, hh = blockIdx.y, qt = blockIdx.x;
    int tid = threadIdx.x;
    int qbase = b * SS + qt * 64;

    for (int i = tid; i < 64 * 16; i += 128) {
        int r = i >> 4, c = (i & 15) << 2;
        *(float4*)&Qs[r][c] = *(const float4*)&q[(size_t)(qbase + r) * HH + hh * 64 + c];
    }
    if (tid < 64) { m_s[tid] = -1e30f; l_s[tid] = 0.f; }
    int qrow = tid >> 1, half = tid & 1, d0 = half * 32;
    float acc[32];
    #pragma unroll
    for (int j = 0; j < 32; j++) acc[j] = 0.f;
    __syncthreads();

    float4 qreg[16];
    #pragma unroll
    for (int i = 0; i < 16; i++) qreg[i] = *(const float4*)&Qs[qrow][i * 4];

    for (int kt = 0; kt < 16; kt++) {
        int kbase = b * SS + kt * 32;
        for (int i = tid; i < 32 * 16; i += 128) {
            int r = i >> 4, c = (i & 15) << 2;
            size_t off = (size_t)(kbase + r) * HH + hh * 64 + c;
            *(float4*)&Ks[r][c] = *(const float4*)&k[off];
            *(float4*)&Vs[r][c] = *(const float4*)&v[off];
        }
        if (tid < 32) msk[tid] = (src[kbase + tid] != 0);
        __syncthreads();

        for (int kk = 0; kk < 16; kk++) {
            int key = half * 16 + kk;
            const float4* kp = (const float4*)&Ks[key][0];
            float s = 0.f;
            #pragma unroll
            for (int i = 0; i < 16; i++) {
                float4 kv = kp[i];
                s += qreg[i].x * kv.x + qreg[i].y * kv.y + qreg[i].z * kv.z + qreg[i].w * kv.w;
            }
            Ps[qrow][key] = msk[key] ? s * 0.125f : -1e10f;
        }
        __syncthreads();

        if (tid < 64) {
            float mt = -1e30f;
            for (int kk = 0; kk < 32; kk++) mt = fmaxf(mt, Ps[tid][kk]);
            float mold = m_s[tid], mnew = fmaxf(mold, mt);
            float sc = expf(mold - mnew);
            float ls = 0.f;
            for (int kk = 0; kk < 32; kk++) {
                float p = expf(Ps[tid][kk] - mnew);
                Ps[tid][kk] = p;
                ls += p;
            }
            m_s[tid] = mnew;
            l_s[tid] = l_s[tid] * sc + ls;
            sc_s[tid] = sc;
        }
        __syncthreads();

        float sc = sc_s[qrow];
        #pragma unroll
        for (int j = 0; j < 32; j++) acc[j] *= sc;
        for (int kk = 0; kk < 32; kk++) {
            float p = Ps[qrow][kk];
            const float4* vp = (const float4*)&Vs[kk][d0];
            #pragma unroll
            for (int j4 = 0; j4 < 8; j4++) {
                float4 vv = vp[j4];
                acc[j4 * 4 + 0] += p * vv.x;
                acc[j4 * 4 + 1] += p * vv.y;
                acc[j4 * 4 + 2] += p * vv.z;
                acc[j4 * 4 + 3] += p * vv.w;
            }
        }
        __syncthreads();
    }

    float inv = 1.f / l_s[qrow];
    float* op = &o[(size_t)(qbase + qrow) * HH + hh * 64 + d0];
    #pragma unroll
    for (int j4 = 0; j4 < 8; j4++) {
        float4 w;
        w.x = acc[j4 * 4 + 0] * inv;
        w.y = acc[j4 * 4 + 1] * inv;
        w.z = acc[j4 * 4 + 2] * inv;
        w.w = acc[j4 * 4 + 3] * inv;
        *(float4*)&op[j4 * 4] = w;
    }
}

// ---------------------------------------------------------------------------
// output: concat(h [N*H], x [N*D])
// ---------------------------------------------------------------------------
__global__ void copy_out_kernel(const float* __restrict__ h, const float* __restrict__ x,
                                float* __restrict__ out) {
    int i = blockIdx.x * blockDim.x + threadIdx.x;
    if (i < NTOK * HH) out[i] = h[i];
    else if (i < NTOK * HH + NTOK * DD) out[i] = x[i - NTOK * HH];
}

// ---------------------------------------------------------------------------
extern "C" void kernel_launch(void* const* d_in, const int* in_sizes, int n_in,
                              void* d_out, int out_size) {
    const int*   src   = (const int*)  d_in[0];
    const int*   nb    = (const int*)  d_in[2];
    const int*   cnt   = (const int*)  d_in[3];
    const float* tint  = (const float*)d_in[4];
    const float* emb   = (const float*)d_in[5];
    const float* timeW = (const float*)d_in[6];
    const float* timeb = (const float*)d_in[7];
    const float* socW  = (const float*)d_in[8];
    const float* socb  = (const float*)d_in[9];
    const float* socg  = (const float*)d_in[10];
    const float* socbe = (const float*)d_in[11];
    const float* projW = (const float*)d_in[12];
    const float* projb = (const float*)d_in[13];
    const float* Wq    = (const float*)d_in[14];
    const float* bq    = (const float*)d_in[15];
    const float* Wk    = (const float*)d_in[16];
    const float* bk    = (const float*)d_in[17];
    const float* Wv    = (const float*)d_in[18];
    const float* bv    = (const float*)d_in[19];
    const float* Wo    = (const float*)d_in[20];
    const float* bo    = (const float*)d_in[21];
    const float* ln1g  = (const float*)d_in[22];
    const float* ln1b  = (const float*)d_in[23];
    const float* ffW1  = (const float*)d_in[24];
    const float* ffb1  = (const float*)d_in[25];
    const float* ffW2  = (const float*)d_in[26];
    const float* ffb2  = (const float*)d_in[27];
    const float* ln2g  = (const float*)d_in[28];
    const float* ln2b  = (const float*)d_in[29];

    float *px, *pagg, *psoc, *ph, *pq, *pk, *pv, *pao, *pt, *pff;
    cudaGetSymbolAddress((void**)&px,   g_x);
    cudaGetSymbolAddress((void**)&pagg, g_agg);
    cudaGetSymbolAddress((void**)&psoc, g_soc);
    cudaGetSymbolAddress((void**)&ph,   g_h);
    cudaGetSymbolAddress((void**)&pq,   g_q);
    cudaGetSymbolAddress((void**)&pk,   g_k);
    cudaGetSymbolAddress((void**)&pv,   g_v);
    cudaGetSymbolAddress((void**)&pao,  g_ao);
    cudaGetSymbolAddress((void**)&pt,   g_t);
    cudaGetSymbolAddress((void**)&pff,  g_ff);

    embed_kernel<<<(NTOK * DD + 255) / 256, 256>>>(src, tint, emb, timeW, timeb, px);
    agg_kernel<<<NTOK, 256>>>(nb, cnt, px, pagg);
    tgemm_kernel<false><<<dim3(DD / 128, NTOK / 128), 256>>>(pagg, socW, socb, psoc, NTOK, DD, DD);
    soc_finish_kernel<<<NTOK, 256>>>(src, cnt, socg, socbe, px, psoc);
    tgemm_kernel<false><<<dim3(HH / 128, NTOK / 128), 256>>>(px, projW, projb, ph, NTOK, HH, DD);

    for (int l = 0; l < LL; l++) {
        const float* wq = Wq + (size_t)l * HH * HH;
        const float* wk = Wk + (size_t)l * HH * HH;
        const float* wv = Wv + (size_t)l * HH * HH;
        const float* wo = Wo + (size_t)l * HH * HH;
        tgemm_kernel<false><<<dim3(HH / 128, NTOK / 128), 256>>>(ph, wq, bq + l * HH, pq, NTOK, HH, HH);
        tgemm_kernel<false><<<dim3(HH / 128, NTOK / 128), 256>>>(ph, wk, bk + l * HH, pk, NTOK, HH, HH);
        tgemm_kernel<false><<<dim3(HH / 128, NTOK / 128), 256>>>(ph, wv, bv + l * HH, pv, NTOK, HH, HH);
        attn_kernel<<<dim3(SS / 64, NHH, BB), 128>>>(pq, pk, pv, src, pao);
        tgemm_kernel<false><<<dim3(HH / 128, NTOK / 128), 256>>>(pao, wo, bo + l * HH, pt, NTOK, HH, HH);
        add_ln512_kernel<<<NTOK, 256>>>(ph, pt, ln1g + l * HH, ln1b + l * HH, ph);
        tgemm_kernel<true><<<dim3(PFF / 128, NTOK / 128), 256>>>(ph, ffW1 + (size_t)l * HH * PFF,
                                                                 ffb1 + l * PFF, pff, NTOK, PFF, HH);
        tgemm_kernel<false><<<dim3(HH / 128, NTOK / 128), 256>>>(pff, ffW2 + (size_t)l * PFF * HH,
                                                                 ffb2 + l * HH, pt, NTOK, HH, PFF);
        add_ln512_kernel<<<NTOK, 256>>>(ph, pt, ln2g + l * HH, ln2b + l * HH, ph);
    }

    int total = NTOK * HH + NTOK * DD;
    copy_out_kernel<<<(total + 255) / 256, 256>>>(ph, px, (float*)d_out);
}

// round 3
// speedup vs baseline: 2.4264x; 1.4334x over previous
#include <cuda_runtime.h>
#include <math.h>
#include <stdint.h>

// Problem constants
#define BB 32
#define SS 512
#define DD 256
#define HH 512
#define NHH 8
#define HDD 64
#define PFF 2048
#define LL 2
#define NTOK (BB*SS)      // 16384
#define NMAXX 15

// Scratch (device globals; no allocation allowed)
__device__ float g_x[NTOK*DD];
__device__ float g_agg[NTOK*DD];
__device__ float g_soc[NTOK*DD];
__device__ float g_h[NTOK*HH];
__device__ float g_q[NTOK*HH];
__device__ float g_k[NTOK*HH];
__device__ float g_v[NTOK*HH];
__device__ float g_ao[NTOK*HH];
__device__ float g_t[NTOK*HH];
__device__ float g_ff[NTOK*PFF];

// ---------------------------------------------------------------------------
// helpers
// ---------------------------------------------------------------------------
__device__ __forceinline__ float to_tf32(float x) {
    uint32_t u;
    asm("cvt.rna.tf32.f32 %0, %1;" : "=r"(u) : "f"(x));
    return __uint_as_float(u);
}

__device__ __forceinline__ void mma_tf32(float* c, const float* a, const float* b) {
    const uint32_t* A = reinterpret_cast<const uint32_t*>(a);
    const uint32_t* B = reinterpret_cast<const uint32_t*>(b);
    asm volatile(
        "mma.sync.aligned.m16n8k8.row.col.f32.tf32.tf32.f32 "
        "{%0,%1,%2,%3}, {%4,%5,%6,%7}, {%8,%9}, {%0,%1,%2,%3};"
        : "+f"(c[0]), "+f"(c[1]), "+f"(c[2]), "+f"(c[3])
        : "r"(A[0]), "r"(A[1]), "r"(A[2]), "r"(A[3]), "r"(B[0]), "r"(B[1]));
}

// ---------------------------------------------------------------------------
// 1) embedding + sinusoidal PE + time-interval encoding
// ---------------------------------------------------------------------------
__global__ void embed_kernel(const int* __restrict__ src, const float* __restrict__ tint,
                             const float* __restrict__ emb, const float* __restrict__ timeW,
                             const float* __restrict__ timeb, float* __restrict__ x) {
    int idx = blockIdx.x * blockDim.x + threadIdx.x;
    if (idx >= NTOK * DD) return;
    int n = idx / DD, d = idx - n * DD;
    int s = n & (SS - 1);
    int tok = src[n];
    float div = expf((float)(d & ~1) * (-9.210340371976184f / (float)DD)); // ln(10000)
    float arg = (float)s * div;
    float pe = (d & 1) ? cosf(arg) : sinf(arg);
    x[idx] = emb[tok * DD + d] + pe + tint[n] * timeW[d] + timeb[d];
}

// ---------------------------------------------------------------------------
// 2) neighbor aggregation: masked mean over <=15 neighbors
// ---------------------------------------------------------------------------
__global__ void agg_kernel(const int* __restrict__ nb, const int* __restrict__ cnt,
                           const float* __restrict__ x, float* __restrict__ agg) {
    int n = blockIdx.x;
    int d = threadIdx.x;
    int c = cnt[n];
    float s = 0.f;
    for (int j = 0; j < c; j++) {
        int m = nb[n * NMAXX + j];
        s += x[m * DD + d];
    }
    int cm = c > 0 ? c : 1;
    agg[n * DD + d] = s / (float)cm;
}

// ---------------------------------------------------------------------------
// TF32 tensor-core GEMM: C = A*B + bias (optional ReLU)
// 128x128 CTA tile, BK=32, 8 warps (2x4), warp tile 64x32, m16n8k8 mma.
// A smem is k-permuted within 8-groups: pos 2t <- k_t, 2t+1 <- k_{t+4},
// so A fragments are conflict-free LDS.64 (row stride 40 -> bank 8g+2t).
// All staging stores are STS.128.
// ---------------------------------------------------------------------------
#define APAD 8   // A row stride = 40 words
#define BPAD 8   // B row stride = 136 words

template<bool RELU>
__global__ __launch_bounds__(256) void tgemm_kernel(
    const float* __restrict__ A, const float* __restrict__ B,
    const float* __restrict__ bias, float* __restrict__ C,
    int M, int Nn, int K) {
    __shared__ float As[128][32 + APAD];
    __shared__ float Bs[32][128 + BPAD];

    int tid = threadIdx.x;
    int lane = tid & 31, warp = tid >> 5;
    int wm = (warp >> 2) * 64;
    int wn = (warp & 3) * 32;
    int g = lane >> 2, t = lane & 3;
    int bm = blockIdx.y * 128, bn = blockIdx.x * 128;

    int arow = tid >> 1;
    int acol0 = (tid & 1) * 16;
    int brow = tid >> 3;
    int bcol0 = (tid & 7) * 4;

    float acc[4][4][4];
    #pragma unroll
    for (int mi = 0; mi < 4; mi++)
        #pragma unroll
        for (int ni = 0; ni < 4; ni++)
            #pragma unroll
            for (int r = 0; r < 4; r++) acc[mi][ni][r] = 0.f;

    const float* Ag = A + (size_t)(bm + arow) * K + acol0;
    const float* Bg = B + (size_t)brow * Nn + bn + bcol0;

    for (int k0 = 0; k0 < K; k0 += 32) {
        // stage A (tf32 + k-permute), 4x STS.128
        #pragma unroll
        for (int j = 0; j < 2; j++) {
            float4 va = *(const float4*)(Ag + k0 + j * 8);
            float4 vb = *(const float4*)(Ag + k0 + j * 8 + 4);
            float4 o0 = make_float4(to_tf32(va.x), to_tf32(vb.x), to_tf32(va.y), to_tf32(vb.y));
            float4 o1 = make_float4(to_tf32(va.z), to_tf32(vb.z), to_tf32(va.w), to_tf32(vb.w));
            *(float4*)&As[arow][acol0 + j * 8]     = o0;
            *(float4*)&As[arow][acol0 + j * 8 + 4] = o1;
        }
        // stage B (tf32), 4x STS.128
        #pragma unroll
        for (int i = 0; i < 4; i++) {
            float4 v = *(const float4*)(Bg + (size_t)k0 * Nn + i * 32);
            float4 w = make_float4(to_tf32(v.x), to_tf32(v.y), to_tf32(v.z), to_tf32(v.w));
            *(float4*)&Bs[brow][bcol0 + i * 32] = w;
        }
        __syncthreads();

        #pragma unroll
        for (int kk = 0; kk < 4; kk++) {
            int k = kk * 8;
            float af[4][4];
            #pragma unroll
            for (int mi = 0; mi < 4; mi++) {
                int r0 = wm + mi * 16 + g;
                float2 p0 = *(const float2*)&As[r0][k + 2 * t];
                float2 p1 = *(const float2*)&As[r0 + 8][k + 2 * t];
                af[mi][0] = p0.x; af[mi][2] = p0.y;
                af[mi][1] = p1.x; af[mi][3] = p1.y;
            }
            float bf[4][2];
            #pragma unroll
            for (int ni = 0; ni < 4; ni++) {
                int c = wn + ni * 8 + g;
                bf[ni][0] = Bs[k + t][c];
                bf[ni][1] = Bs[k + t + 4][c];
            }
            #pragma unroll
            for (int mi = 0; mi < 4; mi++)
                #pragma unroll
                for (int ni = 0; ni < 4; ni++)
                    mma_tf32(acc[mi][ni], af[mi], bf[ni]);
        }
        __syncthreads();
    }

    #pragma unroll
    for (int mi = 0; mi < 4; mi++) {
        int r0 = bm + wm + mi * 16 + g;
        int r1 = r0 + 8;
        #pragma unroll
        for (int ni = 0; ni < 4; ni++) {
            int c = bn + wn + ni * 8 + 2 * t;
            float bx = bias[c], by = bias[c + 1];
            float v0 = acc[mi][ni][0] + bx;
            float v1 = acc[mi][ni][1] + by;
            float v2 = acc[mi][ni][2] + bx;
            float v3 = acc[mi][ni][3] + by;
            if (RELU) {
                v0 = fmaxf(v0, 0.f); v1 = fmaxf(v1, 0.f);
                v2 = fmaxf(v2, 0.f); v3 = fmaxf(v3, 0.f);
            }
            *(float2*)&C[(size_t)r0 * Nn + c] = make_float2(v0, v1);
            *(float2*)&C[(size_t)r1 * Nn + c] = make_float2(v2, v3);
        }
    }
}

// ---------------------------------------------------------------------------
// 3) social block epilogue
// ---------------------------------------------------------------------------
__global__ void soc_finish_kernel(const int* __restrict__ src, const int* __restrict__ cnt,
                                  const float* __restrict__ g, const float* __restrict__ beta,
                                  float* __restrict__ x, const float* __restrict__ socl) {
    __shared__ float red[256];
    int n = blockIdx.x, t = threadIdx.x;
    float flatv = x[n * DD + t];
    float y = flatv + socl[n * DD + t];
    red[t] = y; __syncthreads();
    for (int s = 128; s; s >>= 1) { if (t < s) red[t] += red[t + s]; __syncthreads(); }
    float mu = red[0] * (1.f / DD);
    __syncthreads();
    float e = y - mu;
    red[t] = e * e; __syncthreads();
    for (int s = 128; s; s >>= 1) { if (t < s) red[t] += red[t + s]; __syncthreads(); }
    float rstd = rsqrtf(red[0] * (1.f / DD) + 1e-5f);
    float s1 = fmaxf(e * rstd * g[t] + beta[t], 0.f);
    float soc = (cnt[n] > 0) ? s1 : flatv;
    if (src[n] == 0) soc = 0.f;
    x[n * DD + t] = flatv + 0.2f * soc;
}

// ---------------------------------------------------------------------------
// residual-add + LayerNorm for H=512 rows
// ---------------------------------------------------------------------------
__global__ void add_ln512_kernel(const float* __restrict__ resid, const float* __restrict__ delta,
                                 const float* __restrict__ g, const float* __restrict__ bta,
                                 float* __restrict__ out) {
    __shared__ float red[256];
    int n = blockIdx.x, t = threadIdx.x;
    float y0 = resid[n * 512 + t]       + delta[n * 512 + t];
    float y1 = resid[n * 512 + 256 + t] + delta[n * 512 + 256 + t];
    red[t] = y0 + y1; __syncthreads();
    for (int s = 128; s; s >>= 1) { if (t < s) red[t] += red[t + s]; __syncthreads(); }
    float mu = red[0] * (1.f / 512.f);
    __syncthreads();
    float e0 = y0 - mu, e1 = y1 - mu;
    red[t] = e0 * e0 + e1 * e1; __syncthreads();
    for (int s = 128; s; s >>= 1) { if (t < s) red[t] += red[t + s]; __syncthreads(); }
    float rstd = rsqrtf(red[0] * (1.f / 512.f) + 1e-5f);
    out[n * 512 + t]       = e0 * rstd * g[t] + bta[t];
    out[n * 512 + 256 + t] = e1 * rstd * g[256 + t] + bta[256 + t];
}

// ---------------------------------------------------------------------------
// 4) masked flash attention on tensor cores (tf32 mma, fp32 softmax)
//    block = (qtile 64, head, batch), 256 threads = 8 warps.
//    warp (wr=warp>>1, wc=warp&1): rows 16*wr..+15;
//      QK cols 16*wc..+15 (2 ni tiles); PV out-cols 32*wc..+31 (4 ni tiles).
// ---------------------------------------------------------------------------
__global__ __launch_bounds__(256) void attn_kernel(
    const float* __restrict__ q, const float* __restrict__ k,
    const float* __restrict__ v, const int* __restrict__ src,
    float* __restrict__ o) {
    __shared__ float Qs[64][68];   // bank 4g+t conflict-free frags
    __shared__ float Ks[32][68];
    __shared__ float Vs[32][72];   // bank 8t+g conflict-free frags
    __shared__ float Ps[64][36];   // bank 4g+t conflict-free frags
    __shared__ float m_s[64], l_s[64], sc_s[64];
    __shared__ int msk[32];

    int b = blockIdx.z, hh = blockIdx.y, qt = blockIdx.x;
    int tid = threadIdx.x;
    int lane = tid & 31, warp = tid >> 5;
    int g = lane >> 2, t = lane & 3;
    int wr = warp >> 1, wc = warp & 1;
    int rbase = wr * 16;
    int qbase = b * SS + qt * 64;

    // stage Q (tf32)
    for (int i = tid; i < 64 * 16; i += 256) {
        int r = i >> 4, c = (i & 15) << 2;
        float4 vq = *(const float4*)&q[(size_t)(qbase + r) * HH + hh * 64 + c];
        Qs[r][c + 0] = to_tf32(vq.x);
        Qs[r][c + 1] = to_tf32(vq.y);
        Qs[r][c + 2] = to_tf32(vq.z);
        Qs[r][c + 3] = to_tf32(vq.w);
    }
    if (tid < 64) { m_s[tid] = -1e30f; l_s[tid] = 0.f; }
    __syncthreads();

    // Q fragments to registers: rows rbase+g(+8), all 8 ksteps over d=64
    float qf[8][4];
    #pragma unroll
    for (int kk = 0; kk < 8; kk++) {
        int kb = kk * 8;
        qf[kk][0] = Qs[rbase + g][kb + t];
        qf[kk][1] = Qs[rbase + 8 + g][kb + t];
        qf[kk][2] = Qs[rbase + g][kb + t + 4];
        qf[kk][3] = Qs[rbase + 8 + g][kb + t + 4];
    }

    float acc[4][4];
    #pragma unroll
    for (int ni = 0; ni < 4; ni++)
        #pragma unroll
        for (int r = 0; r < 4; r++) acc[ni][r] = 0.f;

    for (int kt = 0; kt < 16; kt++) {
        int kbase = b * SS + kt * 32;
        // stage K and V tiles (tf32)
        for (int i = tid; i < 32 * 16; i += 256) {
            int r = i >> 4, c = (i & 15) << 2;
            size_t off = (size_t)(kbase + r) * HH + hh * 64 + c;
            float4 kv = *(const float4*)&k[off];
            float4 vv = *(const float4*)&v[off];
            Ks[r][c + 0] = to_tf32(kv.x); Ks[r][c + 1] = to_tf32(kv.y);
            Ks[r][c + 2] = to_tf32(kv.z); Ks[r][c + 3] = to_tf32(kv.w);
            Vs[r][c + 0] = to_tf32(vv.x); Vs[r][c + 1] = to_tf32(vv.y);
            Vs[r][c + 2] = to_tf32(vv.z); Vs[r][c + 3] = to_tf32(vv.w);
        }
        if (tid < 32) msk[tid] = (src[kbase + tid] != 0);
        __syncthreads();

        // S = Q K^T : warp covers rows rbase..+15, cols 16*wc..+15
        float sacc[2][4];
        #pragma unroll
        for (int ni = 0; ni < 2; ni++)
            #pragma unroll
            for (int r = 0; r < 4; r++) sacc[ni][r] = 0.f;
        #pragma unroll
        for (int kk = 0; kk < 8; kk++) {
            int kb = kk * 8;
            float bf[2][2];
            #pragma unroll
            for (int ni = 0; ni < 2; ni++) {
                int c = wc * 16 + ni * 8 + g;        // key index in tile
                bf[ni][0] = Ks[c][kb + t];
                bf[ni][1] = Ks[c][kb + t + 4];
            }
            #pragma unroll
            for (int ni = 0; ni < 2; ni++)
                mma_tf32(sacc[ni], qf[kk], bf[ni]);
        }
        // write S to Ps (scale + mask)
        #pragma unroll
        for (int ni = 0; ni < 2; ni++) {
            int c0 = wc * 16 + ni * 8 + 2 * t;
            int c1 = c0 + 1;
            Ps[rbase + g][c0]     = msk[c0] ? sacc[ni][0] * 0.125f : -1e10f;
            Ps[rbase + g][c1]     = msk[c1] ? sacc[ni][1] * 0.125f : -1e10f;
            Ps[rbase + 8 + g][c0] = msk[c0] ? sacc[ni][2] * 0.125f : -1e10f;
            Ps[rbase + 8 + g][c1] = msk[c1] ? sacc[ni][3] * 0.125f : -1e10f;
        }
        __syncthreads();

        // online softmax, one thread per query row; store p as tf32
        if (tid < 64) {
            float mt = -1e30f;
            #pragma unroll 8
            for (int kk = 0; kk < 32; kk++) mt = fmaxf(mt, Ps[tid][kk]);
            float mold = m_s[tid], mnew = fmaxf(mold, mt);
            float sc = expf(mold - mnew);
            float ls = 0.f;
            #pragma unroll 8
            for (int kk = 0; kk < 32; kk++) {
                float p = expf(Ps[tid][kk] - mnew);
                Ps[tid][kk] = to_tf32(p);
                ls += p;
            }
            m_s[tid] = mnew;
            l_s[tid] = l_s[tid] * sc + ls;
            sc_s[tid] = sc;
        }
        __syncthreads();

        // rescale accumulators
        float sc0 = sc_s[rbase + g], sc1 = sc_s[rbase + 8 + g];
        #pragma unroll
        for (int ni = 0; ni < 4; ni++) {
            acc[ni][0] *= sc0; acc[ni][1] *= sc0;
            acc[ni][2] *= sc1; acc[ni][3] *= sc1;
        }
        // O += P V : K=32 keys, out-cols 32*wc..+31
        #pragma unroll
        for (int kk = 0; kk < 4; kk++) {
            int kb = kk * 8;
            float af[4];
            af[0] = Ps[rbase + g][kb + t];
            af[1] = Ps[rbase + 8 + g][kb + t];
            af[2] = Ps[rbase + g][kb + t + 4];
            af[3] = Ps[rbase + 8 + g][kb + t + 4];
            float bf[4][2];
            #pragma unroll
            for (int ni = 0; ni < 4; ni++) {
                int c = wc * 32 + ni * 8 + g;        // output dim index
                bf[ni][0] = Vs[kb + t][c];
                bf[ni][1] = Vs[kb + t + 4][c];
            }
            #pragma unroll
            for (int ni = 0; ni < 4; ni++)
                mma_tf32(acc[ni], af, bf[ni]);
        }
        __syncthreads();
    }

    float inv0 = 1.f / l_s[rbase + g];
    float inv1 = 1.f / l_s[rbase + 8 + g];
    int row0 = qbase + rbase + g;
    int row1 = row0 + 8;
    #pragma unroll
    for (int ni = 0; ni < 4; ni++) {
        int c = hh * 64 + wc * 32 + ni * 8 + 2 * t;
        *(float2*)&o[(size_t)row0 * HH + c] = make_float2(acc[ni][0] * inv0, acc[ni][1] * inv0);
        *(float2*)&o[(size_t)row1 * HH + c] = make_float2(acc[ni][2] * inv1, acc[ni][3] * inv1);
    }
}

// ---------------------------------------------------------------------------
// output: concat(h [N*H], x [N*D])
// ---------------------------------------------------------------------------
__global__ void copy_out_kernel(const float* __restrict__ h, const float* __restrict__ x,
                                float* __restrict__ out) {
    int i = blockIdx.x * blockDim.x + threadIdx.x;
    if (i < NTOK * HH) out[i] = h[i];
    else if (i < NTOK * HH + NTOK * DD) out[i] = x[i - NTOK * HH];
}

// ---------------------------------------------------------------------------
extern "C" void kernel_launch(void* const* d_in, const int* in_sizes, int n_in,
                              void* d_out, int out_size) {
    const int*   src   = (const int*)  d_in[0];
    const int*   nb    = (const int*)  d_in[2];
    const int*   cnt   = (const int*)  d_in[3];
    const float* tint  = (const float*)d_in[4];
    const float* emb   = (const float*)d_in[5];
    const float* timeW = (const float*)d_in[6];
    const float* timeb = (const float*)d_in[7];
    const float* socW  = (const float*)d_in[8];
    const float* socb  = (const float*)d_in[9];
    const float* socg  = (const float*)d_in[10];
    const float* socbe = (const float*)d_in[11];
    const float* projW = (const float*)d_in[12];
    const float* projb = (const float*)d_in[13];
    const float* Wq    = (const float*)d_in[14];
    const float* bq    = (const float*)d_in[15];
    const float* Wk    = (const float*)d_in[16];
    const float* bk    = (const float*)d_in[17];
    const float* Wv    = (const float*)d_in[18];
    const float* bv    = (const float*)d_in[19];
    const float* Wo    = (const float*)d_in[20];
    const float* bo    = (const float*)d_in[21];
    const float* ln1g  = (const float*)d_in[22];
    const float* ln1b  = (const float*)d_in[23];
    const float* ffW1  = (const float*)d_in[24];
    const float* ffb1  = (const float*)d_in[25];
    const float* ffW2  = (const float*)d_in[26];
    const float* ffb2  = (const float*)d_in[27];
    const float* ln2g  = (const float*)d_in[28];
    const float* ln2b  = (const float*)d_in[29];

    float *px, *pagg, *psoc, *ph, *pq, *pk, *pv, *pao, *pt, *pff;
    cudaGetSymbolAddress((void**)&px,   g_x);
    cudaGetSymbolAddress((void**)&pagg, g_agg);
    cudaGetSymbolAddress((void**)&psoc, g_soc);
    cudaGetSymbolAddress((void**)&ph,   g_h);
    cudaGetSymbolAddress((void**)&pq,   g_q);
    cudaGetSymbolAddress((void**)&pk,   g_k);
    cudaGetSymbolAddress((void**)&pv,   g_v);
    cudaGetSymbolAddress((void**)&pao,  g_ao);
    cudaGetSymbolAddress((void**)&pt,   g_t);
    cudaGetSymbolAddress((void**)&pff,  g_ff);

    embed_kernel<<<(NTOK * DD + 255) / 256, 256>>>(src, tint, emb, timeW, timeb, px);
    agg_kernel<<<NTOK, 256>>>(nb, cnt, px, pagg);
    tgemm_kernel<false><<<dim3(DD / 128, NTOK / 128), 256>>>(pagg, socW, socb, psoc, NTOK, DD, DD);
    soc_finish_kernel<<<NTOK, 256>>>(src, cnt, socg, socbe, px, psoc);
    tgemm_kernel<false><<<dim3(HH / 128, NTOK / 128), 256>>>(px, projW, projb, ph, NTOK, HH, DD);

    for (int l = 0; l < LL; l++) {
        const float* wq = Wq + (size_t)l * HH * HH;
        const float* wk = Wk + (size_t)l * HH * HH;
        const float* wv = Wv + (size_t)l * HH * HH;
        const float* wo = Wo + (size_t)l * HH * HH;
        tgemm_kernel<false><<<dim3(HH / 128, NTOK / 128), 256>>>(ph, wq, bq + l * HH, pq, NTOK, HH, HH);
        tgemm_kernel<false><<<dim3(HH / 128, NTOK / 128), 256>>>(ph, wk, bk + l * HH, pk, NTOK, HH, HH);
        tgemm_kernel<false><<<dim3(HH / 128, NTOK / 128), 256>>>(ph, wv, bv + l * HH, pv, NTOK, HH, HH);
        attn_kernel<<<dim3(SS / 64, NHH, BB), 256>>>(pq, pk, pv, src, pao);
        tgemm_kernel<false><<<dim3(HH / 128, NTOK / 128), 256>>>(pao, wo, bo + l * HH, pt, NTOK, HH, HH);
        add_ln512_kernel<<<NTOK, 256>>>(ph, pt, ln1g + l * HH, ln1b + l * HH, ph);
        tgemm_kernel<true><<<dim3(PFF / 128, NTOK / 128), 256>>>(ph, ffW1 + (size_t)l * HH * PFF,
                                                                 ffb1 + l * PFF, pff, NTOK, PFF, HH);
        tgemm_kernel<false><<<dim3(HH / 128, NTOK / 128), 256>>>(pff, ffW2 + (size_t)l * PFF * HH,
                                                                 ffb2 + l * HH, pt, NTOK, HH, PFF);
        add_ln512_kernel<<<NTOK, 256>>>(ph, pt, ln2g + l * HH, ln2b + l * HH, ph);
    }

    int total = NTOK * HH + NTOK * DD;
    copy_out_kernel<<<(total + 255) / 256, 256>>>(ph, px, (float*)d_out);
}

// round 6
// speedup vs baseline: 2.6102x; 1.0758x over previous
#include <cuda_runtime.h>
#include <math.h>
#include <stdint.h>

// Problem constants
#define BB 32
#define SS 512
#define DD 256
#define HH 512
#define NHH 8
#define HDD 64
#define PFF 2048
#define LL 2
#define NTOK (BB*SS)      // 16384
#define NMAXX 15

// Scratch (device globals; no allocation allowed)
__device__ float g_x[NTOK*DD];
__device__ float g_agg[NTOK*DD];
__device__ float g_soc[NTOK*DD];
__device__ float g_h[NTOK*HH];
__device__ float g_q[NTOK*HH];
__device__ float g_k[NTOK*HH];
__device__ float g_v[NTOK*HH];
__device__ float g_ao[NTOK*HH];
__device__ float g_t[NTOK*HH];
__device__ float g_ff[NTOK*PFF];

// ---------------------------------------------------------------------------
// helpers
// ---------------------------------------------------------------------------
__device__ __forceinline__ float to_tf32(float x) {
    uint32_t u;
    asm("cvt.rna.tf32.f32 %0, %1;" : "=r"(u) : "f"(x));
    return __uint_as_float(u);
}

__device__ __forceinline__ void mma_tf32(float* c, const float* a, const float* b) {
    const uint32_t* A = reinterpret_cast<const uint32_t*>(a);
    const uint32_t* B = reinterpret_cast<const uint32_t*>(b);
    asm volatile(
        "mma.sync.aligned.m16n8k8.row.col.f32.tf32.tf32.f32 "
        "{%0,%1,%2,%3}, {%4,%5,%6,%7}, {%8,%9}, {%0,%1,%2,%3};"
        : "+f"(c[0]), "+f"(c[1]), "+f"(c[2]), "+f"(c[3])
        : "r"(A[0]), "r"(A[1]), "r"(A[2]), "r"(A[3]), "r"(B[0]), "r"(B[1]));
}

// ---------------------------------------------------------------------------
// 1) embedding + sinusoidal PE + time-interval encoding
// ---------------------------------------------------------------------------
__global__ void embed_kernel(const int* __restrict__ src, const float* __restrict__ tint,
                             const float* __restrict__ emb, const float* __restrict__ timeW,
                             const float* __restrict__ timeb, float* __restrict__ x) {
    int idx = blockIdx.x * blockDim.x + threadIdx.x;
    if (idx >= NTOK * DD) return;
    int n = idx / DD, d = idx - n * DD;
    int s = n & (SS - 1);
    int tok = src[n];
    float div = expf((float)(d & ~1) * (-9.210340371976184f / (float)DD)); // ln(10000)
    float arg = (float)s * div;
    float pe = (d & 1) ? cosf(arg) : sinf(arg);
    x[idx] = emb[tok * DD + d] + pe + tint[n] * timeW[d] + timeb[d];
}

// ---------------------------------------------------------------------------
// 2) neighbor aggregation: masked mean over <=15 neighbors
// ---------------------------------------------------------------------------
__global__ void agg_kernel(const int* __restrict__ nb, const int* __restrict__ cnt,
                           const float* __restrict__ x, float* __restrict__ agg) {
    int n = blockIdx.x;
    int d = threadIdx.x;
    int c = cnt[n];
    float s = 0.f;
    for (int j = 0; j < c; j++) {
        int m = nb[n * NMAXX + j];
        s += x[m * DD + d];
    }
    int cm = c > 0 ? c : 1;
    agg[n * DD + d] = s / (float)cm;
}

// ---------------------------------------------------------------------------
// TF32 tensor-core GEMM, double-buffered pipeline.
// 128x128 CTA tile, BK=16, 2 smem stages, 8 warps (2x4), warp tile 64x32.
// A smem k-permuted within 8-groups (pos 2t<-k_t, 2t+1<-k_{t+4}):
//   A row stride 24 words -> frag LDS.64 bank 24g+2t, phase-conflict-free.
// B row stride 136 words -> frag bank 8t+g, conflict-free.
// ---------------------------------------------------------------------------
#define ASTR 24      // 16 + 8 pad
#define BSTR 136     // 128 + 8 pad

template<bool RELU>
__global__ __launch_bounds__(256, 2) void tgemm_kernel(
    const float* __restrict__ A, const float* __restrict__ B,
    const float* __restrict__ bias, float* __restrict__ C,
    int M, int Nn, int K) {
    __shared__ float As[2][128 * ASTR];
    __shared__ float Bs[2][16 * BSTR];

    int tid = threadIdx.x;
    int lane = tid & 31, warp = tid >> 5;
    int wm = (warp >> 2) * 64;
    int wn = (warp & 3) * 32;
    int g = lane >> 2, t = lane & 3;
    int bm = blockIdx.y * 128, bn = blockIdx.x * 128;

    int arow = tid >> 1;            // 2 threads per A row, 8 cols each
    int acol0 = (tid & 1) * 8;
    int brow = tid >> 4;            // 16 threads per B row, 8 cols each
    int bcol0 = (tid & 15) * 8;

    float acc[4][4][4];
    #pragma unroll
    for (int mi = 0; mi < 4; mi++)
        #pragma unroll
        for (int ni = 0; ni < 4; ni++)
            #pragma unroll
            for (int r = 0; r < 4; r++) acc[mi][ni][r] = 0.f;

    const float* Ag = A + (size_t)(bm + arow) * K + acol0;
    const float* Bg = B + (size_t)brow * Nn + bn + bcol0;

    float4 pa0, pa1, pb0, pb1;

    // prologue: load k0=0
    pa0 = *(const float4*)(Ag);
    pa1 = *(const float4*)(Ag + 4);
    pb0 = *(const float4*)(Bg);
    pb1 = *(const float4*)(Bg + 4);
    {
        float4 o0 = make_float4(to_tf32(pa0.x), to_tf32(pa1.x), to_tf32(pa0.y), to_tf32(pa1.y));
        float4 o1 = make_float4(to_tf32(pa0.z), to_tf32(pa1.z), to_tf32(pa0.w), to_tf32(pa1.w));
        *(float4*)&As[0][arow * ASTR + acol0]     = o0;
        *(float4*)&As[0][arow * ASTR + acol0 + 4] = o1;
        float4 w0 = make_float4(to_tf32(pb0.x), to_tf32(pb0.y), to_tf32(pb0.z), to_tf32(pb0.w));
        float4 w1 = make_float4(to_tf32(pb1.x), to_tf32(pb1.y), to_tf32(pb1.z), to_tf32(pb1.w));
        *(float4*)&Bs[0][brow * BSTR + bcol0]     = w0;
        *(float4*)&Bs[0][brow * BSTR + bcol0 + 4] = w1;
    }
    __syncthreads();

    int cur = 0;
    for (int k0 = 16; k0 < K; k0 += 16) {
        // issue next tile's global loads
        pa0 = *(const float4*)(Ag + k0);
        pa1 = *(const float4*)(Ag + k0 + 4);
        pb0 = *(const float4*)(Bg + (size_t)k0 * Nn);
        pb1 = *(const float4*)(Bg + (size_t)k0 * Nn + 4);

        // compute on current stage
        const float* Ac = As[cur];
        const float* Bc = Bs[cur];
        #pragma unroll
        for (int kk = 0; kk < 2; kk++) {
            int kb = kk * 8;
            float af[4][4];
            #pragma unroll
            for (int mi = 0; mi < 4; mi++) {
                int r0 = wm + mi * 16 + g;
                float2 p0 = *(const float2*)&Ac[r0 * ASTR + kb + 2 * t];
                float2 p1 = *(const float2*)&Ac[(r0 + 8) * ASTR + kb + 2 * t];
                af[mi][0] = p0.x; af[mi][2] = p0.y;
                af[mi][1] = p1.x; af[mi][3] = p1.y;
            }
            float bf[4][2];
            #pragma unroll
            for (int ni = 0; ni < 4; ni++) {
                int c = wn + ni * 8 + g;
                bf[ni][0] = Bc[(kb + t) * BSTR + c];
                bf[ni][1] = Bc[(kb + t + 4) * BSTR + c];
            }
            #pragma unroll
            for (int mi = 0; mi < 4; mi++)
                #pragma unroll
                for (int ni = 0; ni < 4; ni++)
                    mma_tf32(acc[mi][ni], af[mi], bf[ni]);
        }

        // store next stage (waits on the LDGs issued above)
        int nxt = cur ^ 1;
        float4 o0 = make_float4(to_tf32(pa0.x), to_tf32(pa1.x), to_tf32(pa0.y), to_tf32(pa1.y));
        float4 o1 = make_float4(to_tf32(pa0.z), to_tf32(pa1.z), to_tf32(pa0.w), to_tf32(pa1.w));
        *(float4*)&As[nxt][arow * ASTR + acol0]     = o0;
        *(float4*)&As[nxt][arow * ASTR + acol0 + 4] = o1;
        float4 w0 = make_float4(to_tf32(pb0.x), to_tf32(pb0.y), to_tf32(pb0.z), to_tf32(pb0.w));
        float4 w1 = make_float4(to_tf32(pb1.x), to_tf32(pb1.y), to_tf32(pb1.z), to_tf32(pb1.w));
        *(float4*)&Bs[nxt][brow * BSTR + bcol0]     = w0;
        *(float4*)&Bs[nxt][brow * BSTR + bcol0 + 4] = w1;
        __syncthreads();
        cur = nxt;
    }

    // last stage compute
    {
        const float* Ac = As[cur];
        const float* Bc = Bs[cur];
        #pragma unroll
        for (int kk = 0; kk < 2; kk++) {
            int kb = kk * 8;
            float af[4][4];
            #pragma unroll
            for (int mi = 0; mi < 4; mi++) {
                int r0 = wm + mi * 16 + g;
                float2 p0 = *(const float2*)&Ac[r0 * ASTR + kb + 2 * t];
                float2 p1 = *(const float2*)&Ac[(r0 + 8) * ASTR + kb + 2 * t];
                af[mi][0] = p0.x; af[mi][2] = p0.y;
                af[mi][1] = p1.x; af[mi][3] = p1.y;
            }
            float bf[4][2];
            #pragma unroll
            for (int ni = 0; ni < 4; ni++) {
                int c = wn + ni * 8 + g;
                bf[ni][0] = Bc[(kb + t) * BSTR + c];
                bf[ni][1] = Bc[(kb + t + 4) * BSTR + c];
            }
            #pragma unroll
            for (int mi = 0; mi < 4; mi++)
                #pragma unroll
                for (int ni = 0; ni < 4; ni++)
                    mma_tf32(acc[mi][ni], af[mi], bf[ni]);
        }
    }

    #pragma unroll
    for (int mi = 0; mi < 4; mi++) {
        int r0 = bm + wm + mi * 16 + g;
        int r1 = r0 + 8;
        #pragma unroll
        for (int ni = 0; ni < 4; ni++) {
            int c = bn + wn + ni * 8 + 2 * t;
            float bx = bias[c], by = bias[c + 1];
            float v0 = acc[mi][ni][0] + bx;
            float v1 = acc[mi][ni][1] + by;
            float v2 = acc[mi][ni][2] + bx;
            float v3 = acc[mi][ni][3] + by;
            if (RELU) {
                v0 = fmaxf(v0, 0.f); v1 = fmaxf(v1, 0.f);
                v2 = fmaxf(v2, 0.f); v3 = fmaxf(v3, 0.f);
            }
            *(float2*)&C[(size_t)r0 * Nn + c] = make_float2(v0, v1);
            *(float2*)&C[(size_t)r1 * Nn + c] = make_float2(v2, v3);
        }
    }
}

// ---------------------------------------------------------------------------
// 3) social block epilogue (warp-shuffle reductions). Also writes final x
//    into the output tail (out_x), since x is not modified afterwards.
// ---------------------------------------------------------------------------
__global__ void soc_finish_kernel(const int* __restrict__ src, const int* __restrict__ cnt,
                                  const float* __restrict__ g, const float* __restrict__ beta,
                                  float* __restrict__ x, const float* __restrict__ socl,
                                  float* __restrict__ out_x) {
    __shared__ float ws[8];
    __shared__ float bc0, bc1;
    int n = blockIdx.x, t = threadIdx.x;
    int lane = t & 31, w = t >> 5;
    float flatv = x[n * DD + t];
    float y = flatv + socl[n * DD + t];
    float s = y;
    #pragma unroll
    for (int o = 16; o; o >>= 1) s += __shfl_xor_sync(0xffffffffu, s, o);
    if (lane == 0) ws[w] = s;
    __syncthreads();
    if (t < 8) {
        float v = ws[t];
        #pragma unroll
        for (int o = 4; o; o >>= 1) v += __shfl_xor_sync(0xffu, v, o);
        if (t == 0) bc0 = v;
    }
    __syncthreads();
    float mu = bc0 * (1.f / DD);
    float e = y - mu;
    s = e * e;
    #pragma unroll
    for (int o = 16; o; o >>= 1) s += __shfl_xor_sync(0xffffffffu, s, o);
    if (lane == 0) ws[w] = s;
    __syncthreads();
    if (t < 8) {
        float v = ws[t];
        #pragma unroll
        for (int o = 4; o; o >>= 1) v += __shfl_xor_sync(0xffu, v, o);
        if (t == 0) bc1 = v;
    }
    __syncthreads();
    float rstd = rsqrtf(bc1 * (1.f / DD) + 1e-5f);
    float s1 = fmaxf(e * rstd * g[t] + beta[t], 0.f);
    float soc = (cnt[n] > 0) ? s1 : flatv;
    if (src[n] == 0) soc = 0.f;
    float xv = flatv + 0.2f * soc;
    x[n * DD + t] = xv;
    out_x[n * DD + t] = xv;
}

// ---------------------------------------------------------------------------
// residual-add + LayerNorm for H=512 rows (warp-shuffle reductions)
// ---------------------------------------------------------------------------
__global__ void add_ln512_kernel(const float* __restrict__ resid, const float* __restrict__ delta,
                                 const float* __restrict__ g, const float* __restrict__ bta,
                                 float* __restrict__ out) {
    __shared__ float ws[8];
    __shared__ float bc0, bc1;
    int n = blockIdx.x, t = threadIdx.x;
    int lane = t & 31, w = t >> 5;
    float y0 = resid[n * 512 + t]       + delta[n * 512 + t];
    float y1 = resid[n * 512 + 256 + t] + delta[n * 512 + 256 + t];
    float s = y0 + y1;
    #pragma unroll
    for (int o = 16; o; o >>= 1) s += __shfl_xor_sync(0xffffffffu, s, o);
    if (lane == 0) ws[w] = s;
    __syncthreads();
    if (t < 8) {
        float v = ws[t];
        #pragma unroll
        for (int o = 4; o; o >>= 1) v += __shfl_xor_sync(0xffu, v, o);
        if (t == 0) bc0 = v;
    }
    __syncthreads();
    float mu = bc0 * (1.f / 512.f);
    float e0 = y0 - mu, e1 = y1 - mu;
    s = e0 * e0 + e1 * e1;
    #pragma unroll
    for (int o = 16; o; o >>= 1) s += __shfl_xor_sync(0xffffffffu, s, o);
    if (lane == 0) ws[w] = s;
    __syncthreads();
    if (t < 8) {
        float v = ws[t];
        #pragma unroll
        for (int o = 4; o; o >>= 1) v += __shfl_xor_sync(0xffu, v, o);
        if (t == 0) bc1 = v;
    }
    __syncthreads();
    float rstd = rsqrtf(bc1 * (1.f / 512.f) + 1e-5f);
    out[n * 512 + t]       = e0 * rstd * g[t] + bta[t];
    out[n * 512 + 256 + t] = e1 * rstd * g[256 + t] + bta[256 + t];
}

// ---------------------------------------------------------------------------
// 4) masked flash attention on tensor cores (tf32 mma, fp32 softmax)
// ---------------------------------------------------------------------------
__global__ __launch_bounds__(256) void attn_kernel(
    const float* __restrict__ q, const float* __restrict__ k,
    const float* __restrict__ v, const int* __restrict__ src,
    float* __restrict__ o) {
    __shared__ float Qs[64][68];
    __shared__ float Ks[32][68];
    __shared__ float Vs[32][72];
    __shared__ float Ps[64][36];
    __shared__ float m_s[64], l_s[64], sc_s[64];
    __shared__ int msk[32];

    int b = blockIdx.z, hh = blockIdx.y, qt = blockIdx.x;
    int tid = threadIdx.x;
    int lane = tid & 31, warp = tid >> 5;
    int g = lane >> 2, t = lane & 3;
    int wr = warp >> 1, wc = warp & 1;
    int rbase = wr * 16;
    int qbase = b * SS + qt * 64;

    for (int i = tid; i < 64 * 16; i += 256) {
        int r = i >> 4, c = (i & 15) << 2;
        float4 vq = *(const float4*)&q[(size_t)(qbase + r) * HH + hh * 64 + c];
        Qs[r][c + 0] = to_tf32(vq.x);
        Qs[r][c + 1] = to_tf32(vq.y);
        Qs[r][c + 2] = to_tf32(vq.z);
        Qs[r][c + 3] = to_tf32(vq.w);
    }
    if (tid < 64) { m_s[tid] = -1e30f; l_s[tid] = 0.f; }
    __syncthreads();

    float qf[8][4];
    #pragma unroll
    for (int kk = 0; kk < 8; kk++) {
        int kb = kk * 8;
        qf[kk][0] = Qs[rbase + g][kb + t];
        qf[kk][1] = Qs[rbase + 8 + g][kb + t];
        qf[kk][2] = Qs[rbase + g][kb + t + 4];
        qf[kk][3] = Qs[rbase + 8 + g][kb + t + 4];
    }

    float acc[4][4];
    #pragma unroll
    for (int ni = 0; ni < 4; ni++)
        #pragma unroll
        for (int r = 0; r < 4; r++) acc[ni][r] = 0.f;

    for (int kt = 0; kt < 16; kt++) {
        int kbase = b * SS + kt * 32;
        for (int i = tid; i < 32 * 16; i += 256) {
            int r = i >> 4, c = (i & 15) << 2;
            size_t off = (size_t)(kbase + r) * HH + hh * 64 + c;
            float4 kv = *(const float4*)&k[off];
            float4 vv = *(const float4*)&v[off];
            Ks[r][c + 0] = to_tf32(kv.x); Ks[r][c + 1] = to_tf32(kv.y);
            Ks[r][c + 2] = to_tf32(kv.z); Ks[r][c + 3] = to_tf32(kv.w);
            Vs[r][c + 0] = to_tf32(vv.x); Vs[r][c + 1] = to_tf32(vv.y);
            Vs[r][c + 2] = to_tf32(vv.z); Vs[r][c + 3] = to_tf32(vv.w);
        }
        if (tid < 32) msk[tid] = (src[kbase + tid] != 0);
        __syncthreads();

        float sacc[2][4];
        #pragma unroll
        for (int ni = 0; ni < 2; ni++)
            #pragma unroll
            for (int r = 0; r < 4; r++) sacc[ni][r] = 0.f;
        #pragma unroll
        for (int kk = 0; kk < 8; kk++) {
            int kb = kk * 8;
            float bf[2][2];
            #pragma unroll
            for (int ni = 0; ni < 2; ni++) {
                int c = wc * 16 + ni * 8 + g;
                bf[ni][0] = Ks[c][kb + t];
                bf[ni][1] = Ks[c][kb + t + 4];
            }
            #pragma unroll
            for (int ni = 0; ni < 2; ni++)
                mma_tf32(sacc[ni], qf[kk], bf[ni]);
        }
        #pragma unroll
        for (int ni = 0; ni < 2; ni++) {
            int c0 = wc * 16 + ni * 8 + 2 * t;
            int c1 = c0 + 1;
            Ps[rbase + g][c0]     = msk[c0] ? sacc[ni][0] * 0.125f : -1e10f;
            Ps[rbase + g][c1]     = msk[c1] ? sacc[ni][1] * 0.125f : -1e10f;
            Ps[rbase + 8 + g][c0] = msk[c0] ? sacc[ni][2] * 0.125f : -1e10f;
            Ps[rbase + 8 + g][c1] = msk[c1] ? sacc[ni][3] * 0.125f : -1e10f;
        }
        __syncthreads();

        if (tid < 64) {
            float mt = -1e30f;
            #pragma unroll 8
            for (int kk = 0; kk < 32; kk++) mt = fmaxf(mt, Ps[tid][kk]);
            float mold = m_s[tid], mnew = fmaxf(mold, mt);
            float sc = expf(mold - mnew);
            float ls = 0.f;
            #pragma unroll 8
            for (int kk = 0; kk < 32; kk++) {
                float p = expf(Ps[tid][kk] - mnew);
                Ps[tid][kk] = to_tf32(p);
                ls += p;
            }
            m_s[tid] = mnew;
            l_s[tid] = l_s[tid] * sc + ls;
            sc_s[tid] = sc;
        }
        __syncthreads();

        float sc0 = sc_s[rbase + g], sc1 = sc_s[rbase + 8 + g];
        #pragma unroll
        for (int ni = 0; ni < 4; ni++) {
            acc[ni][0] *= sc0; acc[ni][1] *= sc0;
            acc[ni][2] *= sc1; acc[ni][3] *= sc1;
        }
        #pragma unroll
        for (int kk = 0; kk < 4; kk++) {
            int kb = kk * 8;
            float af[4];
            af[0] = Ps[rbase + g][kb + t];
            af[1] = Ps[rbase + 8 + g][kb + t];
            af[2] = Ps[rbase + g][kb + t + 4];
            af[3] = Ps[rbase + 8 + g][kb + t + 4];
            float bf[4][2];
            #pragma unroll
            for (int ni = 0; ni < 4; ni++) {
                int c = wc * 32 + ni * 8 + g;
                bf[ni][0] = Vs[kb + t][c];
                bf[ni][1] = Vs[kb + t + 4][c];
            }
            #pragma unroll
            for (int ni = 0; ni < 4; ni++)
                mma_tf32(acc[ni], af, bf[ni]);
        }
        __syncthreads();
    }

    float inv0 = 1.f / l_s[rbase + g];
    float inv1 = 1.f / l_s[rbase + 8 + g];
    int row0 = qbase + rbase + g;
    int row1 = row0 + 8;
    #pragma unroll
    for (int ni = 0; ni < 4; ni++) {
        int c = hh * 64 + wc * 32 + ni * 8 + 2 * t;
        *(float2*)&o[(size_t)row0 * HH + c] = make_float2(acc[ni][0] * inv0, acc[ni][1] * inv0);
        *(float2*)&o[(size_t)row1 * HH + c] = make_float2(acc[ni][2] * inv1, acc[ni][3] * inv1);
    }
}

// ---------------------------------------------------------------------------
extern "C" void kernel_launch(void* const* d_in, const int* in_sizes, int n_in,
                              void* d_out, int out_size) {
    const int*   src   = (const int*)  d_in[0];
    const int*   nb    = (const int*)  d_in[2];
    const int*   cnt   = (const int*)  d_in[3];
    const float* tint  = (const float*)d_in[4];
    const float* emb   = (const float*)d_in[5];
    const float* timeW = (const float*)d_in[6];
    const float* timeb = (const float*)d_in[7];
    const float* socW  = (const float*)d_in[8];
    const float* socb  = (const float*)d_in[9];
    const float* socg  = (const float*)d_in[10];
    const float* socbe = (const float*)d_in[11];
    const float* projW = (const float*)d_in[12];
    const float* projb = (const float*)d_in[13];
    const float* Wq    = (const float*)d_in[14];
    const float* bq    = (const float*)d_in[15];
    const float* Wk    = (const float*)d_in[16];
    const float* bk    = (const float*)d_in[17];
    const float* Wv    = (const float*)d_in[18];
    const float* bv    = (const float*)d_in[19];
    const float* Wo    = (const float*)d_in[20];
    const float* bo    = (const float*)d_in[21];
    const float* ln1g  = (const float*)d_in[22];
    const float* ln1b  = (const float*)d_in[23];
    const float* ffW1  = (const float*)d_in[24];
    const float* ffb1  = (const float*)d_in[25];
    const float* ffW2  = (const float*)d_in[26];
    const float* ffb2  = (const float*)d_in[27];
    const float* ln2g  = (const float*)d_in[28];
    const float* ln2b  = (const float*)d_in[29];

    float *px, *pagg, *psoc, *ph, *pq, *pk, *pv, *pao, *pt, *pff;
    cudaGetSymbolAddress((void**)&px,   g_x);
    cudaGetSymbolAddress((void**)&pagg, g_agg);
    cudaGetSymbolAddress((void**)&psoc, g_soc);
    cudaGetSymbolAddress((void**)&ph,   g_h);
    cudaGetSymbolAddress((void**)&pq,   g_q);
    cudaGetSymbolAddress((void**)&pk,   g_k);
    cudaGetSymbolAddress((void**)&pv,   g_v);
    cudaGetSymbolAddress((void**)&pao,  g_ao);
    cudaGetSymbolAddress((void**)&pt,   g_t);
    cudaGetSymbolAddress((void**)&pff,  g_ff);

    float* out_h = (float*)d_out;                 // [NTOK*HH]
    float* out_x = (float*)d_out + NTOK * HH;     // [NTOK*DD]

    embed_kernel<<<(NTOK * DD + 255) / 256, 256>>>(src, tint, emb, timeW, timeb, px);
    agg_kernel<<<NTOK, 256>>>(nb, cnt, px, pagg);
    tgemm_kernel<false><<<dim3(DD / 128, NTOK / 128), 256>>>(pagg, socW, socb, psoc, NTOK, DD, DD);
    soc_finish_kernel<<<NTOK, 256>>>(src, cnt, socg, socbe, px, psoc, out_x);
    tgemm_kernel<false><<<dim3(HH / 128, NTOK / 128), 256>>>(px, projW, projb, ph, NTOK, HH, DD);

    for (int l = 0; l < LL; l++) {
        const float* wq = Wq + (size_t)l * HH * HH;
        const float* wk = Wk + (size_t)l * HH * HH;
        const float* wv = Wv + (size_t)l * HH * HH;
        const float* wo = Wo + (size_t)l * HH * HH;
        tgemm_kernel<false><<<dim3(HH / 128, NTOK / 128), 256>>>(ph, wq, bq + l * HH, pq, NTOK, HH, HH);
        tgemm_kernel<false><<<dim3(HH / 128, NTOK / 128), 256>>>(ph, wk, bk + l * HH, pk, NTOK, HH, HH);
        tgemm_kernel<false><<<dim3(HH / 128, NTOK / 128), 256>>>(ph, wv, bv + l * HH, pv, NTOK, HH, HH);
        attn_kernel<<<dim3(SS / 64, NHH, BB), 256>>>(pq, pk, pv, src, pao);
        tgemm_kernel<false><<<dim3(HH / 128, NTOK / 128), 256>>>(pao, wo, bo + l * HH, pt, NTOK, HH, HH);
        add_ln512_kernel<<<NTOK, 256>>>(ph, pt, ln1g + l * HH, ln1b + l * HH, ph);
        tgemm_kernel<true><<<dim3(PFF / 128, NTOK / 128), 256>>>(ph, ffW1 + (size_t)l * HH * PFF,
                                                                 ffb1 + l * PFF, pff, NTOK, PFF, HH);
        tgemm_kernel<false><<<dim3(HH / 128, NTOK / 128), 256>>>(pff, ffW2 + (size_t)l * PFF * HH,
                                                                 ffb2 + l * HH, pt, NTOK, HH, PFF);
        // last LN of the last layer writes h directly into the output head
        float* lnout = (l == LL - 1) ? out_h : ph;
        add_ln512_kernel<<<NTOK, 256>>>(ph, pt, ln2g + l * HH, ln2b + l * HH, lnout);
    }
}